// round 1
// baseline (speedup 1.0000x reference)
#include <cuda_runtime.h>
#include <math.h>

#define DIM   768
#define DFF   3072
#define HEADS 12
#define DK    64
#define MAXTOK 8192

// ---- scratch (device globals; no allocation allowed) ----
__device__ float g_h   [MAXTOK * DIM];        // ln1 out, reused for ln2 out
__device__ float g_qkv [MAXTOK * 3 * DIM];
__device__ float g_attn[MAXTOK * DIM];
__device__ float g_x1  [MAXTOK * DIM];        // x + attn_proj
__device__ float g_ff  [MAXTOK * DFF];        // gelu(fc1)

// ============================================================
// LayerNorm: one block per token, 256 threads, 3 elems/thread
// ============================================================
__global__ __launch_bounds__(256) void ln_kernel(
    const float* __restrict__ x, const float* __restrict__ w,
    const float* __restrict__ b, float* __restrict__ y)
{
    const int t = blockIdx.x;
    const float* xr = x + (size_t)t * DIM;
    float v[3];
    float s1 = 0.f, s2 = 0.f;
#pragma unroll
    for (int i = 0; i < 3; i++) {
        v[i] = xr[threadIdx.x + i * 256];
        s1 += v[i];
        s2 += v[i] * v[i];
    }
#pragma unroll
    for (int off = 16; off; off >>= 1) {
        s1 += __shfl_xor_sync(0xffffffffu, s1, off);
        s2 += __shfl_xor_sync(0xffffffffu, s2, off);
    }
    __shared__ float r1[8], r2[8];
    __shared__ float smu, srstd;
    const int wid = threadIdx.x >> 5, lane = threadIdx.x & 31;
    if (lane == 0) { r1[wid] = s1; r2[wid] = s2; }
    __syncthreads();
    if (threadIdx.x == 0) {
        float a = 0.f, c = 0.f;
#pragma unroll
        for (int i = 0; i < 8; i++) { a += r1[i]; c += r2[i]; }
        const float mu  = a * (1.0f / DIM);
        const float var = c * (1.0f / DIM) - mu * mu;
        smu = mu;
        srstd = rsqrtf(var + 1e-5f);
    }
    __syncthreads();
    const float mu = smu, rstd = srstd;
    float* yr = y + (size_t)t * DIM;
#pragma unroll
    for (int i = 0; i < 3; i++) {
        const int c = threadIdx.x + i * 256;
        yr[c] = (v[i] - mu) * rstd * w[c] + b[c];
    }
}

// ============================================================
// SGEMM (NT): C[m,n] = sum_k A[m,k] * B[n,k] + bias[n]  (+epi)
// A: [M,K] row-major, B: [N,K] row-major (weights), both K-contig.
// 128x128x16 tiles, 256 threads, 8x8 per-thread microkernel.
// EPI: 0 = bias only, 1 = bias + residual, 2 = bias + exact GELU
// ============================================================
#define GBK 16
#define GPAD 132

template <int EPI>
__global__ __launch_bounds__(256) void sgemm_nt(
    const float* __restrict__ A, const float* __restrict__ B,
    const float* __restrict__ bias, const float* __restrict__ res,
    float* __restrict__ C, int M, int N, int K)
{
    __shared__ float As[GBK][GPAD];
    __shared__ float Bs[GBK][GPAD];
    const int bm = blockIdx.y * 128;
    const int bn = blockIdx.x * 128;
    const int tid = threadIdx.x;
    const int tm = tid >> 4;          // 0..15
    const int tn = tid & 15;          // 0..15
    const int lrow = tid >> 2;        // 0..63
    const int lcol = (tid & 3) << 2;  // 0,4,8,12

    float acc[8][8] = {};
    const float* Ap = A + (size_t)bm * K;
    const float* Bp = B + (size_t)bn * K;

    for (int k0 = 0; k0 < K; k0 += GBK) {
#pragma unroll
        for (int i = 0; i < 2; i++) {
            const int row = lrow + i * 64;
            float4 a4 = *(const float4*)(Ap + (size_t)row * K + k0 + lcol);
            As[lcol + 0][row] = a4.x;
            As[lcol + 1][row] = a4.y;
            As[lcol + 2][row] = a4.z;
            As[lcol + 3][row] = a4.w;
            float4 b4 = *(const float4*)(Bp + (size_t)row * K + k0 + lcol);
            Bs[lcol + 0][row] = b4.x;
            Bs[lcol + 1][row] = b4.y;
            Bs[lcol + 2][row] = b4.z;
            Bs[lcol + 3][row] = b4.w;
        }
        __syncthreads();
#pragma unroll
        for (int kk = 0; kk < GBK; kk++) {
            float a[8], b[8];
            *(float4*)(a)     = *(const float4*)&As[kk][tm * 4];
            *(float4*)(a + 4) = *(const float4*)&As[kk][64 + tm * 4];
            *(float4*)(b)     = *(const float4*)&Bs[kk][tn * 4];
            *(float4*)(b + 4) = *(const float4*)&Bs[kk][64 + tn * 4];
#pragma unroll
            for (int i = 0; i < 8; i++)
#pragma unroll
                for (int j = 0; j < 8; j++)
                    acc[i][j] = fmaf(a[i], b[j], acc[i][j]);
        }
        __syncthreads();
    }

#pragma unroll
    for (int i = 0; i < 8; i++) {
        const int r = bm + ((i < 4) ? (tm * 4 + i) : (64 + tm * 4 + i - 4));
#pragma unroll
        for (int j = 0; j < 8; j++) {
            const int c = bn + ((j < 4) ? (tn * 4 + j) : (64 + tn * 4 + j - 4));
            float v = acc[i][j] + bias[c];
            if (EPI == 1) v += res[(size_t)r * N + c];
            if (EPI == 2) v = 0.5f * v * (1.0f + erff(v * 0.70710678118654752f));
            C[(size_t)r * N + c] = v;
        }
    }
}

// ============================================================
// Flash attention, fp32. One block per (b, h, 64-query tile).
// 256 threads; per kv tile: S = Q K^T (smem gemm), online softmax,
// O += P V (smem gemm). Q/K stored d-major, V/P key-major; all
// compute LDS are float4 and conflict-free in quarter-warp phases.
// Softmax scale folded into Q at load time.
// ============================================================
#define FSTRIDE 68
#define FLASH_SMEM (4 * 64 * FSTRIDE * 4)

__global__ __launch_bounds__(256) void flash_kernel(
    const float* __restrict__ qkv, float* __restrict__ out)
{
    extern __shared__ float sm[];
    float* Qs = sm;                    // [d][row]
    float* Ks = Qs + 64 * FSTRIDE;     // [d][key]
    float* Vs = Ks + 64 * FSTRIDE;     // [key][d]
    float* Ps = Vs + 64 * FSTRIDE;     // [key][row]

    const int bh = blockIdx.y;
    const int b = bh / HEADS, h = bh % HEADS;
    const int q0 = blockIdx.x * 64;
    const float* base = qkv + (size_t)b * 1024 * (3 * DIM);

    const int tid = threadIdx.x;
    const int tm = tid >> 4;          // 0..15 (row group)
    const int tn = tid & 15;          // 0..15 (col group)
    const int lr = tid >> 2;          // 0..63
    const int lc = (tid & 3) << 4;    // 0,16,32,48

    const float scale = 0.125f;       // dk^-0.5

    // load Q tile transposed, pre-scaled
    {
        const float* src = base + (size_t)(q0 + lr) * (3 * DIM) + h * DK + lc;
#pragma unroll
        for (int u = 0; u < 4; u++) {
            float4 v = *(const float4*)(src + u * 4);
            Qs[(lc + u * 4 + 0) * FSTRIDE + lr] = v.x * scale;
            Qs[(lc + u * 4 + 1) * FSTRIDE + lr] = v.y * scale;
            Qs[(lc + u * 4 + 2) * FSTRIDE + lr] = v.z * scale;
            Qs[(lc + u * 4 + 3) * FSTRIDE + lr] = v.w * scale;
        }
    }

    float m_i[4], l_i[4], o[4][4] = {};
#pragma unroll
    for (int i = 0; i < 4; i++) { m_i[i] = -1e30f; l_i[i] = 0.f; }

    for (int kt = 0; kt < 1024 / 64; kt++) {
        __syncthreads();  // previous iteration's readers of Ks/Vs/Ps done
        {
            const size_t roff = (size_t)(kt * 64 + lr) * (3 * DIM);
            const float* ksrc = base + roff + DIM + h * DK + lc;
            const float* vsrc = base + roff + 2 * DIM + h * DK + lc;
#pragma unroll
            for (int u = 0; u < 4; u++) {
                float4 v = *(const float4*)(ksrc + u * 4);
                Ks[(lc + u * 4 + 0) * FSTRIDE + lr] = v.x;
                Ks[(lc + u * 4 + 1) * FSTRIDE + lr] = v.y;
                Ks[(lc + u * 4 + 2) * FSTRIDE + lr] = v.z;
                Ks[(lc + u * 4 + 3) * FSTRIDE + lr] = v.w;
                *(float4*)&Vs[lr * FSTRIDE + lc + u * 4] =
                    *(const float4*)(vsrc + u * 4);
            }
        }
        __syncthreads();

        // S = Q K^T (already scaled)
        float s[4][4] = {};
#pragma unroll 8
        for (int d = 0; d < DK; d++) {
            float4 a  = *(const float4*)&Qs[d * FSTRIDE + tm * 4];
            float4 bb = *(const float4*)&Ks[d * FSTRIDE + tn * 4];
            s[0][0] = fmaf(a.x, bb.x, s[0][0]); s[0][1] = fmaf(a.x, bb.y, s[0][1]);
            s[0][2] = fmaf(a.x, bb.z, s[0][2]); s[0][3] = fmaf(a.x, bb.w, s[0][3]);
            s[1][0] = fmaf(a.y, bb.x, s[1][0]); s[1][1] = fmaf(a.y, bb.y, s[1][1]);
            s[1][2] = fmaf(a.y, bb.z, s[1][2]); s[1][3] = fmaf(a.y, bb.w, s[1][3]);
            s[2][0] = fmaf(a.z, bb.x, s[2][0]); s[2][1] = fmaf(a.z, bb.y, s[2][1]);
            s[2][2] = fmaf(a.z, bb.z, s[2][2]); s[2][3] = fmaf(a.z, bb.w, s[2][3]);
            s[3][0] = fmaf(a.w, bb.x, s[3][0]); s[3][1] = fmaf(a.w, bb.y, s[3][1]);
            s[3][2] = fmaf(a.w, bb.z, s[3][2]); s[3][3] = fmaf(a.w, bb.w, s[3][3]);
        }

        // online softmax (row stats reduced across the 16 tn lanes)
#pragma unroll
        for (int i = 0; i < 4; i++) {
            float mx = fmaxf(fmaxf(s[i][0], s[i][1]), fmaxf(s[i][2], s[i][3]));
#pragma unroll
            for (int off = 8; off; off >>= 1)
                mx = fmaxf(mx, __shfl_xor_sync(0xffffffffu, mx, off));
            const float mnew = fmaxf(m_i[i], mx);
            const float fac = __expf(m_i[i] - mnew);
            float rsum = 0.f;
#pragma unroll
            for (int j = 0; j < 4; j++) {
                s[i][j] = __expf(s[i][j] - mnew);
                rsum += s[i][j];
            }
#pragma unroll
            for (int off = 8; off; off >>= 1)
                rsum += __shfl_xor_sync(0xffffffffu, rsum, off);
            l_i[i] = l_i[i] * fac + rsum;
            m_i[i] = mnew;
            o[i][0] *= fac; o[i][1] *= fac; o[i][2] *= fac; o[i][3] *= fac;
        }

        // stash P transposed: Ps[key][row]
#pragma unroll
        for (int i = 0; i < 4; i++)
#pragma unroll
            for (int j = 0; j < 4; j++)
                Ps[(tn * 4 + j) * FSTRIDE + tm * 4 + i] = s[i][j];
        __syncthreads();

        // O += P V
#pragma unroll 8
        for (int kk = 0; kk < 64; kk++) {
            float4 p = *(const float4*)&Ps[kk * FSTRIDE + tm * 4];
            float4 v = *(const float4*)&Vs[kk * FSTRIDE + tn * 4];
            o[0][0] = fmaf(p.x, v.x, o[0][0]); o[0][1] = fmaf(p.x, v.y, o[0][1]);
            o[0][2] = fmaf(p.x, v.z, o[0][2]); o[0][3] = fmaf(p.x, v.w, o[0][3]);
            o[1][0] = fmaf(p.y, v.x, o[1][0]); o[1][1] = fmaf(p.y, v.y, o[1][1]);
            o[1][2] = fmaf(p.y, v.z, o[1][2]); o[1][3] = fmaf(p.y, v.w, o[1][3]);
            o[2][0] = fmaf(p.z, v.x, o[2][0]); o[2][1] = fmaf(p.z, v.y, o[2][1]);
            o[2][2] = fmaf(p.z, v.z, o[2][2]); o[2][3] = fmaf(p.z, v.w, o[2][3]);
            o[3][0] = fmaf(p.w, v.x, o[3][0]); o[3][1] = fmaf(p.w, v.y, o[3][1]);
            o[3][2] = fmaf(p.w, v.z, o[3][2]); o[3][3] = fmaf(p.w, v.w, o[3][3]);
        }
    }

    // write out [token, h*64 + d], dividing by row sum
#pragma unroll
    for (int i = 0; i < 4; i++) {
        const float inv = 1.0f / l_i[i];
        const size_t row = (size_t)(b * 1024 + q0 + tm * 4 + i) * DIM + h * DK;
#pragma unroll
        for (int j = 0; j < 4; j++)
            out[row + tn * 4 + j] = o[i][j] * inv;
    }
}

// ============================================================
// launch
// ============================================================
extern "C" void kernel_launch(void* const* d_in, const int* in_sizes, int n_in,
                              void* d_out, int out_size)
{
    const float* x      = (const float*)d_in[0];
    const float* ln1_w  = (const float*)d_in[1];
    const float* ln1_b  = (const float*)d_in[2];
    const float* qkv_w  = (const float*)d_in[3];
    const float* qkv_b  = (const float*)d_in[4];
    const float* proj_w = (const float*)d_in[5];
    const float* proj_b = (const float*)d_in[6];
    const float* ln2_w  = (const float*)d_in[7];
    const float* ln2_b  = (const float*)d_in[8];
    const float* fc1_w  = (const float*)d_in[9];
    const float* fc1_b  = (const float*)d_in[10];
    const float* fc2_w  = (const float*)d_in[11];
    const float* fc2_b  = (const float*)d_in[12];
    float* out = (float*)d_out;

    const int M = in_sizes[0] / DIM;    // 8192 tokens
    const int B = M / 1024;             // 8

    float *h, *qkv, *attn, *x1, *ff;
    cudaGetSymbolAddress((void**)&h,    g_h);
    cudaGetSymbolAddress((void**)&qkv,  g_qkv);
    cudaGetSymbolAddress((void**)&attn, g_attn);
    cudaGetSymbolAddress((void**)&x1,   g_x1);
    cudaGetSymbolAddress((void**)&ff,   g_ff);

    cudaFuncSetAttribute((const void*)flash_kernel,
                         cudaFuncAttributeMaxDynamicSharedMemorySize, FLASH_SMEM);

    // 1) ln1
    ln_kernel<<<M, 256>>>(x, ln1_w, ln1_b, h);
    // 2) qkv = h @ qkv_w^T + qkv_b
    sgemm_nt<0><<<dim3((3 * DIM) / 128, M / 128), 256>>>(
        h, qkv_w, qkv_b, nullptr, qkv, M, 3 * DIM, DIM);
    // 3) attention
    flash_kernel<<<dim3(1024 / 64, B * HEADS), 256, FLASH_SMEM>>>(qkv, attn);
    // 4) x1 = x + attn @ proj_w^T + proj_b
    sgemm_nt<1><<<dim3(DIM / 128, M / 128), 256>>>(
        attn, proj_w, proj_b, x, x1, M, DIM, DIM);
    // 5) ln2
    ln_kernel<<<M, 256>>>(x1, ln2_w, ln2_b, h);
    // 6) ff = gelu(h @ fc1_w^T + fc1_b)
    sgemm_nt<2><<<dim3(DFF / 128, M / 128), 256>>>(
        h, fc1_w, fc1_b, nullptr, ff, M, DFF, DIM);
    // 7) out = x1 + ff @ fc2_w^T + fc2_b
    sgemm_nt<1><<<dim3(DIM / 128, M / 128), 256>>>(
        ff, fc2_w, fc2_b, x1, out, M, DIM, DFF);
}

// round 5
// speedup vs baseline: 2.4589x; 2.4589x over previous
#include <cuda_runtime.h>
#include <cuda_fp16.h>
#include <math.h>
#include <stdint.h>

#define DIM   768
#define DFF   3072
#define HEADS 12
#define DK    64
#define MAXTOK 8192

// ---------------- device scratch (no allocation allowed) ----------------
__device__ __half g_act[MAXTOK * DIM];     // fp16 activations (ln1 out / attn out / ln2 out)
__device__ __half g_ff [MAXTOK * DFF];     // fp16 gelu(fc1) out
__device__ float  g_qkv[MAXTOK * 3 * DIM];
__device__ float  g_x1 [MAXTOK * DIM];
__device__ __half g_wq [3*DIM * DIM];
__device__ __half g_wp [DIM   * DIM];
__device__ __half g_w1 [DFF   * DIM];
__device__ __half g_w2 [DIM   * DFF];

// ---------------- helpers ----------------
__device__ __forceinline__ uint32_t smem_u32(const void* p){
    uint32_t a;
    asm("{ .reg .u64 t; cvta.to.shared.u64 t, %1; cvt.u32.u64 %0, t; }":"=r"(a):"l"(p));
    return a;
}
#define SWZ(o) ((o) ^ (((o)>>3)&0x70))

__device__ __forceinline__ void cp16(uint32_t d, const void* s){
    asm volatile("cp.async.cg.shared.global [%0], [%1], 16;"::"r"(d),"l"(s):"memory");
}
__device__ __forceinline__ void cp_commit(){ asm volatile("cp.async.commit_group;":::"memory"); }
template<int N> __device__ __forceinline__ void cp_wait(){
    asm volatile("cp.async.wait_group %0;"::"n"(N):"memory");
}
__device__ __forceinline__ uint32_t lds32(uint32_t a){
    uint32_t v; asm volatile("ld.shared.b32 %0, [%1];" : "=r"(v) : "r"(a)); return v;
}
__device__ __forceinline__ void mma16816(float* d, const uint32_t* a, const uint32_t* b){
    asm volatile(
        "mma.sync.aligned.m16n8k16.row.col.f32.f16.f16.f32 "
        "{%0,%1,%2,%3}, {%4,%5,%6,%7}, {%8,%9}, {%0,%1,%2,%3};\n"
        : "+f"(d[0]), "+f"(d[1]), "+f"(d[2]), "+f"(d[3])
        : "r"(a[0]), "r"(a[1]), "r"(a[2]), "r"(a[3]), "r"(b[0]), "r"(b[1]));
}

// ============================================================
// weight repack: fp32 -> fp16
// ============================================================
__global__ __launch_bounds__(256) void pack_w(const float* __restrict__ w,
                                              __half* __restrict__ o, int total){
    int i = blockIdx.x * 256 + threadIdx.x;
    if (i < total) o[i] = __float2half(w[i]);
}

// ============================================================
// LayerNorm -> fp16
// ============================================================
__global__ __launch_bounds__(256) void ln_pack(
    const float* __restrict__ x, const float* __restrict__ w,
    const float* __restrict__ b, __half* __restrict__ y)
{
    const int t = blockIdx.x;
    const float* xr = x + (size_t)t * DIM;
    float v[3];
    float s1 = 0.f, s2 = 0.f;
#pragma unroll
    for (int i = 0; i < 3; i++) {
        v[i] = xr[threadIdx.x + i * 256];
        s1 += v[i];
        s2 += v[i] * v[i];
    }
#pragma unroll
    for (int off = 16; off; off >>= 1) {
        s1 += __shfl_xor_sync(0xffffffffu, s1, off);
        s2 += __shfl_xor_sync(0xffffffffu, s2, off);
    }
    __shared__ float r1[8], r2[8];
    __shared__ float smu, srstd;
    const int wid = threadIdx.x >> 5, lane = threadIdx.x & 31;
    if (lane == 0) { r1[wid] = s1; r2[wid] = s2; }
    __syncthreads();
    if (threadIdx.x == 0) {
        float a = 0.f, c = 0.f;
#pragma unroll
        for (int i = 0; i < 8; i++) { a += r1[i]; c += r2[i]; }
        const float mu  = a * (1.0f / DIM);
        const float var = c * (1.0f / DIM) - mu * mu;
        smu = mu;
        srstd = rsqrtf(var + 1e-5f);
    }
    __syncthreads();
    const float mu = smu, rstd = srstd;
    __half* yr = y + (size_t)t * DIM;
#pragma unroll
    for (int i = 0; i < 3; i++) {
        const int c = threadIdx.x + i * 256;
        yr[c] = __float2half((v[i] - mu) * rstd * w[c] + b[c]);
    }
}

// ============================================================
// HMMA GEMM: C[m,n] = A[m,:] . B[n,:]  (A fp16 [M][K], B fp16 [N][K])
// 128x128x64 block tile, 8 warps (2x4), warp tile 64x32.
// Double-buffered cp.async. SW128-swizzled smem (128B rows of 64 fp16).
// EPI 0: +bias -> fp32 | EPI 1: +bias+res -> fp32 | EPI 2: +bias, GELU -> fp16
// ============================================================
#define GSM_STAGE 32768                 // A 16KB + B 16KB
#define GSM_TOTAL (2*GSM_STAGE)

template <int EPI>
__global__ __launch_bounds__(256) void hgemm(
    const __half* __restrict__ A, const __half* __restrict__ B,
    const float* __restrict__ bias, const float* __restrict__ res,
    float* __restrict__ Co, __half* __restrict__ Cp,
    int N, int K)
{
    extern __shared__ char smem[];
    const uint32_t sb = smem_u32(smem);
    const int tid = threadIdx.x;
    const int wid = tid >> 5, lane = tid & 31;
    const int wm = wid & 1;          // 0..1  (m: 2 x 64)
    const int wn = wid >> 1;         // 0..3  (n: 4 x 32)
    const int r  = lane >> 2;        // 0..7
    const int c2 = (lane & 3) * 2;   // 0,2,4,6
    const int bm = blockIdx.y * 128, bn = blockIdx.x * 128;
    const int NIT = K / 64;

    auto load_tile = [&](int it){
        const uint32_t st = sb + (uint32_t)(it & 1) * GSM_STAGE;
        const int k0 = it * 64;
        const __half* Ab = A + (size_t)bm * K + k0;
        const __half* Bb = B + (size_t)bn * K + k0;
#pragma unroll
        for (int i = 0; i < 4; i++){
            const int chunk = tid + i * 256;     // 0..1023
            const int rr = chunk >> 3;
            const int cb = (chunk & 7) * 16;
            const uint32_t so = SWZ((uint32_t)(rr * 128 + cb));
            cp16(st + so,         (const char*)(Ab + (size_t)rr * K) + cb);
            cp16(st + 16384 + so, (const char*)(Bb + (size_t)rr * K) + cb);
        }
    };

    float acc[4][4][4] = {};

    load_tile(0); cp_commit();
    load_tile(1); cp_commit();

    for (int it = 0; it < NIT; it++){
        cp_wait<1>();
        __syncthreads();
        const uint32_t sA = sb + (uint32_t)(it & 1) * GSM_STAGE;
        const uint32_t sB = sA + 16384;
#pragma unroll
        for (int ks = 0; ks < 4; ks++){
            const int koff = ks * 16;
            uint32_t a[4][4], b[4][2];
#pragma unroll
            for (int mt = 0; mt < 4; mt++){
                const int row = wm * 64 + mt * 16 + r;
                const uint32_t b0 = (uint32_t)(row * 128 + (koff + c2) * 2);
                a[mt][0] = lds32(sA + SWZ(b0));
                a[mt][1] = lds32(sA + SWZ(b0 + 8 * 128));
                a[mt][2] = lds32(sA + SWZ(b0 + 16));
                a[mt][3] = lds32(sA + SWZ(b0 + 8 * 128 + 16));
            }
#pragma unroll
            for (int nt = 0; nt < 4; nt++){
                const int n = wn * 32 + nt * 8 + r;
                const uint32_t b0 = (uint32_t)(n * 128 + (koff + c2) * 2);
                b[nt][0] = lds32(sB + SWZ(b0));
                b[nt][1] = lds32(sB + SWZ(b0 + 16));
            }
#pragma unroll
            for (int mt = 0; mt < 4; mt++)
#pragma unroll
                for (int nt = 0; nt < 4; nt++)
                    mma16816(acc[mt][nt], a[mt], b[nt]);
        }
        __syncthreads();
        if (it + 2 < NIT) load_tile(it + 2);
        cp_commit();
    }

    // ---- epilogue: direct from accumulators ----
#pragma unroll
    for (int mt = 0; mt < 4; mt++){
#pragma unroll
        for (int nt = 0; nt < 4; nt++){
            const int row0 = bm + wm * 64 + mt * 16 + r;
            const int col  = bn + wn * 32 + nt * 8 + c2;
            const float b0 = bias[col], b1 = bias[col + 1];
            const float* d = acc[mt][nt];
#pragma unroll
            for (int hh = 0; hh < 2; hh++){
                const int rr = row0 + hh * 8;
                float v0 = d[hh * 2 + 0] + b0;
                float v1 = d[hh * 2 + 1] + b1;
                if (EPI == 1) {
                    const float2 rv = *(const float2*)&res[(size_t)rr * N + col];
                    v0 += rv.x; v1 += rv.y;
                }
                if (EPI == 0 || EPI == 1) {
                    float2 o = make_float2(v0, v1);
                    *(float2*)&Co[(size_t)rr * N + col] = o;
                } else {
                    v0 = 0.5f * v0 * (1.0f + erff(v0 * 0.70710678118654752f));
                    v1 = 0.5f * v1 * (1.0f + erff(v1 * 0.70710678118654752f));
                    *(__half2*)&Cp[(size_t)rr * N + col] = __floats2half2_rn(v0, v1);
                }
            }
        }
    }
}

// ============================================================
// Flash attention fp32 (proven), epilogue writes fp16
// ============================================================
#define FSTRIDE 68
#define FLASH_SMEM (4 * 64 * FSTRIDE * 4)

__global__ __launch_bounds__(256) void flash_kernel(
    const float* __restrict__ qkv, __half* __restrict__ outp)
{
    extern __shared__ float sm[];
    float* Qs = sm;
    float* Ks = Qs + 64 * FSTRIDE;
    float* Vs = Ks + 64 * FSTRIDE;
    float* Ps = Vs + 64 * FSTRIDE;

    const int bh = blockIdx.y;
    const int b = bh / HEADS, h = bh % HEADS;
    const int q0 = blockIdx.x * 64;
    const float* base = qkv + (size_t)b * 1024 * (3 * DIM);

    const int tid = threadIdx.x;
    const int tm = tid >> 4;
    const int tn = tid & 15;
    const int lr = tid >> 2;
    const int lc = (tid & 3) << 4;

    const float scale = 0.125f;
    {
        const float* src = base + (size_t)(q0 + lr) * (3 * DIM) + h * DK + lc;
#pragma unroll
        for (int u = 0; u < 4; u++) {
            float4 v = *(const float4*)(src + u * 4);
            Qs[(lc + u * 4 + 0) * FSTRIDE + lr] = v.x * scale;
            Qs[(lc + u * 4 + 1) * FSTRIDE + lr] = v.y * scale;
            Qs[(lc + u * 4 + 2) * FSTRIDE + lr] = v.z * scale;
            Qs[(lc + u * 4 + 3) * FSTRIDE + lr] = v.w * scale;
        }
    }

    float m_i[4], l_i[4], o[4][4] = {};
#pragma unroll
    for (int i = 0; i < 4; i++) { m_i[i] = -1e30f; l_i[i] = 0.f; }

    for (int kt = 0; kt < 1024 / 64; kt++) {
        __syncthreads();
        {
            const size_t roff = (size_t)(kt * 64 + lr) * (3 * DIM);
            const float* ksrc = base + roff + DIM + h * DK + lc;
            const float* vsrc = base + roff + 2 * DIM + h * DK + lc;
#pragma unroll
            for (int u = 0; u < 4; u++) {
                float4 v = *(const float4*)(ksrc + u * 4);
                Ks[(lc + u * 4 + 0) * FSTRIDE + lr] = v.x;
                Ks[(lc + u * 4 + 1) * FSTRIDE + lr] = v.y;
                Ks[(lc + u * 4 + 2) * FSTRIDE + lr] = v.z;
                Ks[(lc + u * 4 + 3) * FSTRIDE + lr] = v.w;
                *(float4*)&Vs[lr * FSTRIDE + lc + u * 4] =
                    *(const float4*)(vsrc + u * 4);
            }
        }
        __syncthreads();

        float s[4][4] = {};
#pragma unroll 8
        for (int d = 0; d < DK; d++) {
            float4 a  = *(const float4*)&Qs[d * FSTRIDE + tm * 4];
            float4 bb = *(const float4*)&Ks[d * FSTRIDE + tn * 4];
            s[0][0] = fmaf(a.x, bb.x, s[0][0]); s[0][1] = fmaf(a.x, bb.y, s[0][1]);
            s[0][2] = fmaf(a.x, bb.z, s[0][2]); s[0][3] = fmaf(a.x, bb.w, s[0][3]);
            s[1][0] = fmaf(a.y, bb.x, s[1][0]); s[1][1] = fmaf(a.y, bb.y, s[1][1]);
            s[1][2] = fmaf(a.y, bb.z, s[1][2]); s[1][3] = fmaf(a.y, bb.w, s[1][3]);
            s[2][0] = fmaf(a.z, bb.x, s[2][0]); s[2][1] = fmaf(a.z, bb.y, s[2][1]);
            s[2][2] = fmaf(a.z, bb.z, s[2][2]); s[2][3] = fmaf(a.z, bb.w, s[2][3]);
            s[3][0] = fmaf(a.w, bb.x, s[3][0]); s[3][1] = fmaf(a.w, bb.y, s[3][1]);
            s[3][2] = fmaf(a.w, bb.z, s[3][2]); s[3][3] = fmaf(a.w, bb.w, s[3][3]);
        }

#pragma unroll
        for (int i = 0; i < 4; i++) {
            float mx = fmaxf(fmaxf(s[i][0], s[i][1]), fmaxf(s[i][2], s[i][3]));
#pragma unroll
            for (int off = 8; off; off >>= 1)
                mx = fmaxf(mx, __shfl_xor_sync(0xffffffffu, mx, off));
            const float mnew = fmaxf(m_i[i], mx);
            const float fac = __expf(m_i[i] - mnew);
            float rsum = 0.f;
#pragma unroll
            for (int j = 0; j < 4; j++) {
                s[i][j] = __expf(s[i][j] - mnew);
                rsum += s[i][j];
            }
#pragma unroll
            for (int off = 8; off; off >>= 1)
                rsum += __shfl_xor_sync(0xffffffffu, rsum, off);
            l_i[i] = l_i[i] * fac + rsum;
            m_i[i] = mnew;
            o[i][0] *= fac; o[i][1] *= fac; o[i][2] *= fac; o[i][3] *= fac;
        }

#pragma unroll
        for (int i = 0; i < 4; i++)
#pragma unroll
            for (int j = 0; j < 4; j++)
                Ps[(tn * 4 + j) * FSTRIDE + tm * 4 + i] = s[i][j];
        __syncthreads();

#pragma unroll 8
        for (int kk = 0; kk < 64; kk++) {
            float4 p = *(const float4*)&Ps[kk * FSTRIDE + tm * 4];
            float4 v = *(const float4*)&Vs[kk * FSTRIDE + tn * 4];
            o[0][0] = fmaf(p.x, v.x, o[0][0]); o[0][1] = fmaf(p.x, v.y, o[0][1]);
            o[0][2] = fmaf(p.x, v.z, o[0][2]); o[0][3] = fmaf(p.x, v.w, o[0][3]);
            o[1][0] = fmaf(p.y, v.x, o[1][0]); o[1][1] = fmaf(p.y, v.y, o[1][1]);
            o[1][2] = fmaf(p.y, v.z, o[1][2]); o[1][3] = fmaf(p.y, v.w, o[1][3]);
            o[2][0] = fmaf(p.z, v.x, o[2][0]); o[2][1] = fmaf(p.z, v.y, o[2][1]);
            o[2][2] = fmaf(p.z, v.z, o[2][2]); o[2][3] = fmaf(p.z, v.w, o[2][3]);
            o[3][0] = fmaf(p.w, v.x, o[3][0]); o[3][1] = fmaf(p.w, v.y, o[3][1]);
            o[3][2] = fmaf(p.w, v.z, o[3][2]); o[3][3] = fmaf(p.w, v.w, o[3][3]);
        }
    }

#pragma unroll
    for (int i = 0; i < 4; i++) {
        const float inv = 1.0f / l_i[i];
        const size_t gr = (size_t)(b * 1024 + q0 + tm * 4 + i);
        __half* rp = outp + gr * DIM + h * DK + tn * 4;
#pragma unroll
        for (int j = 0; j < 4; j++)
            rp[j] = __float2half(o[i][j] * inv);
    }
}

// ============================================================
// launch
// ============================================================
extern "C" void kernel_launch(void* const* d_in, const int* in_sizes, int n_in,
                              void* d_out, int out_size)
{
    const float* x      = (const float*)d_in[0];
    const float* ln1_w  = (const float*)d_in[1];
    const float* ln1_b  = (const float*)d_in[2];
    const float* qkv_w  = (const float*)d_in[3];
    const float* qkv_b  = (const float*)d_in[4];
    const float* proj_w = (const float*)d_in[5];
    const float* proj_b = (const float*)d_in[6];
    const float* ln2_w  = (const float*)d_in[7];
    const float* ln2_b  = (const float*)d_in[8];
    const float* fc1_w  = (const float*)d_in[9];
    const float* fc1_b  = (const float*)d_in[10];
    const float* fc2_w  = (const float*)d_in[11];
    const float* fc2_b  = (const float*)d_in[12];
    float* out = (float*)d_out;

    const int M = in_sizes[0] / DIM;   // 8192
    const int B = M / 1024;

    __half *act, *ff, *wq, *wp, *w1, *w2;
    float *qkvf, *x1f;
    cudaGetSymbolAddress((void**)&act,  g_act);
    cudaGetSymbolAddress((void**)&ff,   g_ff);
    cudaGetSymbolAddress((void**)&qkvf, g_qkv);
    cudaGetSymbolAddress((void**)&x1f,  g_x1);
    cudaGetSymbolAddress((void**)&wq,   g_wq);
    cudaGetSymbolAddress((void**)&wp,   g_wp);
    cudaGetSymbolAddress((void**)&w1,   g_w1);
    cudaGetSymbolAddress((void**)&w2,   g_w2);

    cudaFuncSetAttribute((const void*)flash_kernel,
                         cudaFuncAttributeMaxDynamicSharedMemorySize, FLASH_SMEM);
    cudaFuncSetAttribute((const void*)hgemm<0>,
                         cudaFuncAttributeMaxDynamicSharedMemorySize, GSM_TOTAL);
    cudaFuncSetAttribute((const void*)hgemm<1>,
                         cudaFuncAttributeMaxDynamicSharedMemorySize, GSM_TOTAL);
    cudaFuncSetAttribute((const void*)hgemm<2>,
                         cudaFuncAttributeMaxDynamicSharedMemorySize, GSM_TOTAL);

    // weight repack fp32 -> fp16
    pack_w<<<(3*DIM*DIM + 255)/256, 256>>>(qkv_w,  wq, 3*DIM*DIM);
    pack_w<<<(DIM*DIM   + 255)/256, 256>>>(proj_w, wp, DIM*DIM);
    pack_w<<<(DFF*DIM   + 255)/256, 256>>>(fc1_w,  w1, DFF*DIM);
    pack_w<<<(DIM*DFF   + 255)/256, 256>>>(fc2_w,  w2, DIM*DFF);

    // 1) ln1 -> fp16 act
    ln_pack<<<M, 256>>>(x, ln1_w, ln1_b, act);
    // 2) qkv = act @ Wqkv^T + b  (fp32 out)
    hgemm<0><<<dim3((3*DIM)/128, M/128), 256, GSM_TOTAL>>>(
        act, wq, qkv_b, nullptr, qkvf, nullptr, 3*DIM, DIM);
    // 3) attention -> fp16 act
    flash_kernel<<<dim3(1024/64, B*HEADS), 256, FLASH_SMEM>>>(qkvf, act);
    // 4) x1 = x + act @ Wproj^T + b
    hgemm<1><<<dim3(DIM/128, M/128), 256, GSM_TOTAL>>>(
        act, wp, proj_b, x, x1f, nullptr, DIM, DIM);
    // 5) ln2 -> fp16 act
    ln_pack<<<M, 256>>>(x1f, ln2_w, ln2_b, act);
    // 6) ff = gelu(act @ Wfc1^T + b)  (fp16 out)
    hgemm<2><<<dim3(DFF/128, M/128), 256, GSM_TOTAL>>>(
        act, w1, fc1_b, nullptr, nullptr, ff, DFF, DIM);
    // 7) out = x1 + ff @ Wfc2^T + b
    hgemm<1><<<dim3(DIM/128, M/128), 256, GSM_TOTAL>>>(
        ff, w2, fc2_b, x1f, out, nullptr, DIM, DFF);
}

// round 6
// speedup vs baseline: 5.3746x; 2.1858x over previous
#include <cuda_runtime.h>
#include <cuda_fp16.h>
#include <math.h>
#include <stdint.h>

#define DIM   768
#define DFF   3072
#define HEADS 12
#define DK    64
#define MAXTOK 8192

// ---------------- device scratch (no allocation allowed) ----------------
__device__ __half g_act [MAXTOK * DIM];     // fp16 activations
__device__ __half g_ff  [MAXTOK * DFF];     // fp16 gelu(fc1)
__device__ __half g_qkvh[MAXTOK * 3 * DIM]; // fp16 qkv
__device__ float  g_x1  [MAXTOK * DIM];
__device__ __half g_wq  [3*DIM * DIM];
__device__ __half g_wp  [DIM   * DIM];
__device__ __half g_w1  [DFF   * DIM];
__device__ __half g_w2  [DIM   * DFF];

// ---------------- helpers ----------------
__device__ __forceinline__ uint32_t smem_u32(const void* p){
    uint32_t a;
    asm("{ .reg .u64 t; cvta.to.shared.u64 t, %1; cvt.u32.u64 %0, t; }":"=r"(a):"l"(p));
    return a;
}
#define SWZ(o) ((o) ^ (((o)>>3)&0x70))

__device__ __forceinline__ void cp16(uint32_t d, const void* s){
    asm volatile("cp.async.cg.shared.global [%0], [%1], 16;"::"r"(d),"l"(s):"memory");
}
__device__ __forceinline__ void cp_commit(){ asm volatile("cp.async.commit_group;":::"memory"); }
template<int N> __device__ __forceinline__ void cp_wait(){
    asm volatile("cp.async.wait_group %0;"::"n"(N):"memory");
}
__device__ __forceinline__ uint32_t lds32(uint32_t a){
    uint32_t v; asm volatile("ld.shared.b32 %0, [%1];" : "=r"(v) : "r"(a)); return v;
}
__device__ __forceinline__ void mma16816(float* d, const uint32_t* a, const uint32_t* b){
    asm volatile(
        "mma.sync.aligned.m16n8k16.row.col.f32.f16.f16.f32 "
        "{%0,%1,%2,%3}, {%4,%5,%6,%7}, {%8,%9}, {%0,%1,%2,%3};\n"
        : "+f"(d[0]), "+f"(d[1]), "+f"(d[2]), "+f"(d[3])
        : "r"(a[0]), "r"(a[1]), "r"(a[2]), "r"(a[3]), "r"(b[0]), "r"(b[1]));
}
__device__ __forceinline__ void ldmx2t(uint32_t& r0, uint32_t& r1, uint32_t addr){
    asm volatile("ldmatrix.sync.aligned.m8n8.x2.trans.shared.b16 {%0,%1}, [%2];"
        : "=r"(r0), "=r"(r1) : "r"(addr));
}

// ============================================================
// weight repack: fp32 -> fp16
// ============================================================
__global__ __launch_bounds__(256) void pack_w(const float* __restrict__ w,
                                              __half* __restrict__ o, int total){
    int i = blockIdx.x * 256 + threadIdx.x;
    if (i < total) o[i] = __float2half(w[i]);
}

// ============================================================
// LayerNorm -> fp16
// ============================================================
__global__ __launch_bounds__(256) void ln_pack(
    const float* __restrict__ x, const float* __restrict__ w,
    const float* __restrict__ b, __half* __restrict__ y)
{
    const int t = blockIdx.x;
    const float* xr = x + (size_t)t * DIM;
    float v[3];
    float s1 = 0.f, s2 = 0.f;
#pragma unroll
    for (int i = 0; i < 3; i++) {
        v[i] = xr[threadIdx.x + i * 256];
        s1 += v[i];
        s2 += v[i] * v[i];
    }
#pragma unroll
    for (int off = 16; off; off >>= 1) {
        s1 += __shfl_xor_sync(0xffffffffu, s1, off);
        s2 += __shfl_xor_sync(0xffffffffu, s2, off);
    }
    __shared__ float r1[8], r2[8];
    __shared__ float smu, srstd;
    const int wid = threadIdx.x >> 5, lane = threadIdx.x & 31;
    if (lane == 0) { r1[wid] = s1; r2[wid] = s2; }
    __syncthreads();
    if (threadIdx.x == 0) {
        float a = 0.f, c = 0.f;
#pragma unroll
        for (int i = 0; i < 8; i++) { a += r1[i]; c += r2[i]; }
        const float mu  = a * (1.0f / DIM);
        const float var = c * (1.0f / DIM) - mu * mu;
        smu = mu;
        srstd = rsqrtf(var + 1e-5f);
    }
    __syncthreads();
    const float mu = smu, rstd = srstd;
    __half* yr = y + (size_t)t * DIM;
#pragma unroll
    for (int i = 0; i < 3; i++) {
        const int c = threadIdx.x + i * 256;
        yr[c] = __float2half((v[i] - mu) * rstd * w[c] + b[c]);
    }
}

// ============================================================
// HMMA GEMM (as round 5, proven).
// EPI 0: +bias->fp32 | 1: +bias+res->fp32 | 2: +bias,GELU->fp16 | 3: +bias->fp16
// ============================================================
#define GSM_STAGE 32768
#define GSM_TOTAL (2*GSM_STAGE)

template <int EPI>
__global__ __launch_bounds__(256) void hgemm(
    const __half* __restrict__ A, const __half* __restrict__ B,
    const float* __restrict__ bias, const float* __restrict__ res,
    float* __restrict__ Co, __half* __restrict__ Cp,
    int N, int K)
{
    extern __shared__ char smem[];
    const uint32_t sb = smem_u32(smem);
    const int tid = threadIdx.x;
    const int wid = tid >> 5, lane = tid & 31;
    const int wm = wid & 1;
    const int wn = wid >> 1;
    const int r  = lane >> 2;
    const int c2 = (lane & 3) * 2;
    const int bm = blockIdx.y * 128, bn = blockIdx.x * 128;
    const int NIT = K / 64;

    auto load_tile = [&](int it){
        const uint32_t st = sb + (uint32_t)(it & 1) * GSM_STAGE;
        const int k0 = it * 64;
        const __half* Ab = A + (size_t)bm * K + k0;
        const __half* Bb = B + (size_t)bn * K + k0;
#pragma unroll
        for (int i = 0; i < 4; i++){
            const int chunk = tid + i * 256;
            const int rr = chunk >> 3;
            const int cb = (chunk & 7) * 16;
            const uint32_t so = SWZ((uint32_t)(rr * 128 + cb));
            cp16(st + so,         (const char*)(Ab + (size_t)rr * K) + cb);
            cp16(st + 16384 + so, (const char*)(Bb + (size_t)rr * K) + cb);
        }
    };

    float acc[4][4][4] = {};

    load_tile(0); cp_commit();
    load_tile(1); cp_commit();

    for (int it = 0; it < NIT; it++){
        cp_wait<1>();
        __syncthreads();
        const uint32_t sA = sb + (uint32_t)(it & 1) * GSM_STAGE;
        const uint32_t sB = sA + 16384;
#pragma unroll
        for (int ks = 0; ks < 4; ks++){
            const int koff = ks * 16;
            uint32_t a[4][4], b[4][2];
#pragma unroll
            for (int mt = 0; mt < 4; mt++){
                const int row = wm * 64 + mt * 16 + r;
                const uint32_t b0 = (uint32_t)(row * 128 + (koff + c2) * 2);
                a[mt][0] = lds32(sA + SWZ(b0));
                a[mt][1] = lds32(sA + SWZ(b0 + 8 * 128));
                a[mt][2] = lds32(sA + SWZ(b0 + 16));
                a[mt][3] = lds32(sA + SWZ(b0 + 8 * 128 + 16));
            }
#pragma unroll
            for (int nt = 0; nt < 4; nt++){
                const int n = wn * 32 + nt * 8 + r;
                const uint32_t b0 = (uint32_t)(n * 128 + (koff + c2) * 2);
                b[nt][0] = lds32(sB + SWZ(b0));
                b[nt][1] = lds32(sB + SWZ(b0 + 16));
            }
#pragma unroll
            for (int mt = 0; mt < 4; mt++)
#pragma unroll
                for (int nt = 0; nt < 4; nt++)
                    mma16816(acc[mt][nt], a[mt], b[nt]);
        }
        __syncthreads();
        if (it + 2 < NIT) load_tile(it + 2);
        cp_commit();
    }

#pragma unroll
    for (int mt = 0; mt < 4; mt++){
#pragma unroll
        for (int nt = 0; nt < 4; nt++){
            const int row0 = bm + wm * 64 + mt * 16 + r;
            const int col  = bn + wn * 32 + nt * 8 + c2;
            const float b0 = bias[col], b1 = bias[col + 1];
            const float* d = acc[mt][nt];
#pragma unroll
            for (int hh = 0; hh < 2; hh++){
                const int rr = row0 + hh * 8;
                float v0 = d[hh * 2 + 0] + b0;
                float v1 = d[hh * 2 + 1] + b1;
                if (EPI == 1) {
                    const float2 rv = *(const float2*)&res[(size_t)rr * N + col];
                    v0 += rv.x; v1 += rv.y;
                }
                if (EPI == 0 || EPI == 1) {
                    float2 o = make_float2(v0, v1);
                    *(float2*)&Co[(size_t)rr * N + col] = o;
                } else if (EPI == 2) {
                    v0 = 0.5f * v0 * (1.0f + erff(v0 * 0.70710678118654752f));
                    v1 = 0.5f * v1 * (1.0f + erff(v1 * 0.70710678118654752f));
                    *(__half2*)&Cp[(size_t)rr * N + col] = __floats2half2_rn(v0, v1);
                } else {
                    *(__half2*)&Cp[(size_t)rr * N + col] = __floats2half2_rn(v0, v1);
                }
            }
        }
    }
}

// ============================================================
// flash2: HMMA flash attention, fp16 in/out, fp32 softmax.
// Grid (8 q-tiles, 96 bh). 8 warps, warp = 16 q-rows.
// S = Q K^T via mma.m16n8k16; C-frags of S convert in-register to
// A-frags of P; P V via ldmatrix.x2.trans B-frags. K/V double-buffered.
// ============================================================
#define FL_SMEM 49152   // Q 16K | K0 8K | K1 8K | V0 8K | V1 8K

__global__ __launch_bounds__(256) void flash2(
    const __half* __restrict__ qkv, __half* __restrict__ outp)
{
    extern __shared__ char smc[];
    const uint32_t sb = smem_u32(smc);
    const uint32_t Qs  = sb;
    const uint32_t Ks0 = sb + 16384, Ks1 = sb + 24576;
    const uint32_t Vs0 = sb + 32768, Vs1 = sb + 40960;

    const int tid = threadIdx.x, w = tid >> 5, lane = tid & 31;
    const int r = lane >> 2, c2 = (lane & 3) * 2;
    const int bh = blockIdx.y;
    const int b = bh / HEADS, h = bh % HEADS;
    const int q0 = blockIdx.x * 128;
    const __half* base = qkv + (size_t)b * 1024 * (3 * DIM) + h * DK;

    // Q tile 128x64 -> swizzled smem
#pragma unroll
    for (int i = 0; i < 4; i++){
        const int chunk = tid + i * 256;
        const int row = chunk >> 3, cb = (chunk & 7) * 16;
        cp16(Qs + SWZ((uint32_t)(row * 128 + cb)),
             (const char*)(base + (size_t)(q0 + row) * (3 * DIM)) + cb);
    }

    auto loadKV = [&](int t){
        const uint32_t sk = (t & 1) ? Ks1 : Ks0;
        const uint32_t sv = (t & 1) ? Vs1 : Vs0;
        const __half* kb = base + DIM     + (size_t)(t * 64) * (3 * DIM);
        const __half* vb = base + 2 * DIM + (size_t)(t * 64) * (3 * DIM);
#pragma unroll
        for (int i = 0; i < 2; i++){
            const int chunk = tid + i * 256;
            const int row = chunk >> 3, cb = (chunk & 7) * 16;
            const uint32_t so = SWZ((uint32_t)(row * 128 + cb));
            cp16(sk + so, (const char*)(kb + (size_t)row * (3 * DIM)) + cb);
            cp16(sv + so, (const char*)(vb + (size_t)row * (3 * DIM)) + cb);
        }
    };

    loadKV(0); cp_commit();      // group: Q + KV0
    loadKV(1); cp_commit();      // group: KV1

    uint32_t aq[4][4];
    float o[8][4] = {};
    float m0 = -1e30f, m1 = -1e30f, l0 = 0.f, l1 = 0.f;
    const int qrow = w * 16 + r;
    const uint32_t lsel = (uint32_t)(lane & 15);
    const uint32_t vsw  = (uint32_t)((lane & 7) << 4);

    for (int t = 0; t < 16; t++){
        cp_wait<1>();
        __syncthreads();
        if (t == 0){
            const __half2 sc = __half2half2(__float2half(0.125f));
#pragma unroll
            for (int kc = 0; kc < 4; kc++){
                const uint32_t b0 = (uint32_t)(qrow * 128 + (kc * 16 + c2) * 2);
                aq[kc][0] = lds32(Qs + SWZ(b0));
                aq[kc][1] = lds32(Qs + SWZ(b0 + 8 * 128));
                aq[kc][2] = lds32(Qs + SWZ(b0 + 16));
                aq[kc][3] = lds32(Qs + SWZ(b0 + 8 * 128 + 16));
#pragma unroll
                for (int u = 0; u < 4; u++){
                    __half2 hv = *(__half2*)&aq[kc][u];
                    hv = __hmul2(hv, sc);
                    aq[kc][u] = *(uint32_t*)&hv;
                }
            }
        }
        const uint32_t sK = (t & 1) ? Ks1 : Ks0;
        const uint32_t sV = (t & 1) ? Vs1 : Vs0;

        // ---- S = Q K^T ----
        float sf[8][4] = {};
#pragma unroll
        for (int kc = 0; kc < 4; kc++){
#pragma unroll
            for (int j = 0; j < 8; j++){
                uint32_t bb[2];
                const uint32_t b0 = (uint32_t)((j * 8 + r) * 128 + (kc * 16 + c2) * 2);
                bb[0] = lds32(sK + SWZ(b0));
                bb[1] = lds32(sK + SWZ(b0 + 16));
                mma16816(sf[j], aq[kc], bb);
            }
        }

        // ---- online softmax (rows qrow and qrow+8) ----
        float mx0 = -1e30f, mx1 = -1e30f;
#pragma unroll
        for (int j = 0; j < 8; j++){
            mx0 = fmaxf(mx0, fmaxf(sf[j][0], sf[j][1]));
            mx1 = fmaxf(mx1, fmaxf(sf[j][2], sf[j][3]));
        }
        mx0 = fmaxf(mx0, __shfl_xor_sync(0xffffffffu, mx0, 1));
        mx0 = fmaxf(mx0, __shfl_xor_sync(0xffffffffu, mx0, 2));
        mx1 = fmaxf(mx1, __shfl_xor_sync(0xffffffffu, mx1, 1));
        mx1 = fmaxf(mx1, __shfl_xor_sync(0xffffffffu, mx1, 2));
        const float mn0 = fmaxf(m0, mx0), mn1 = fmaxf(m1, mx1);
        const float f0 = __expf(m0 - mn0), f1 = __expf(m1 - mn1);
        float s0 = 0.f, s1 = 0.f;
#pragma unroll
        for (int j = 0; j < 8; j++){
            sf[j][0] = __expf(sf[j][0] - mn0);
            sf[j][1] = __expf(sf[j][1] - mn0);
            sf[j][2] = __expf(sf[j][2] - mn1);
            sf[j][3] = __expf(sf[j][3] - mn1);
            s0 += sf[j][0] + sf[j][1];
            s1 += sf[j][2] + sf[j][3];
        }
        s0 += __shfl_xor_sync(0xffffffffu, s0, 1);
        s0 += __shfl_xor_sync(0xffffffffu, s0, 2);
        s1 += __shfl_xor_sync(0xffffffffu, s1, 1);
        s1 += __shfl_xor_sync(0xffffffffu, s1, 2);
        l0 = l0 * f0 + s0;  l1 = l1 * f1 + s1;
        m0 = mn0;           m1 = mn1;
#pragma unroll
        for (int j = 0; j < 8; j++){
            o[j][0] *= f0; o[j][1] *= f0;
            o[j][2] *= f1; o[j][3] *= f1;
        }

        // ---- S C-frags -> P A-frags (in register) ----
        uint32_t pa[4][4];
#pragma unroll
        for (int kc = 0; kc < 4; kc++){
            __half2 h0 = __floats2half2_rn(sf[2*kc][0],   sf[2*kc][1]);
            __half2 h1 = __floats2half2_rn(sf[2*kc][2],   sf[2*kc][3]);
            __half2 h2 = __floats2half2_rn(sf[2*kc+1][0], sf[2*kc+1][1]);
            __half2 h3 = __floats2half2_rn(sf[2*kc+1][2], sf[2*kc+1][3]);
            pa[kc][0] = *(uint32_t*)&h0;
            pa[kc][1] = *(uint32_t*)&h1;
            pa[kc][2] = *(uint32_t*)&h2;
            pa[kc][3] = *(uint32_t*)&h3;
        }

        // ---- O += P V  (V B-frags via ldmatrix.trans) ----
#pragma unroll
        for (int kc = 0; kc < 4; kc++){
#pragma unroll
            for (int j = 0; j < 8; j++){
                uint32_t bb[2];
                const uint32_t addr = sV + (uint32_t)((kc * 16 + lsel) * 128)
                                         + ((uint32_t)(16 * j) ^ vsw);
                ldmx2t(bb[0], bb[1], addr);
                mma16816(o[j], pa[kc], bb);
            }
        }

        __syncthreads();
        if (t + 2 < 16) loadKV(t + 2);
        cp_commit();
    }

    // ---- epilogue ----
    const float inv0 = 1.0f / l0, inv1 = 1.0f / l1;
    __half* p0 = outp + (size_t)(b * 1024 + q0 + qrow) * DIM + h * DK;
    __half* p1 = p0 + 8 * DIM;
#pragma unroll
    for (int j = 0; j < 8; j++){
        *(__half2*)(p0 + j * 8 + c2) = __floats2half2_rn(o[j][0] * inv0, o[j][1] * inv0);
        *(__half2*)(p1 + j * 8 + c2) = __floats2half2_rn(o[j][2] * inv1, o[j][3] * inv1);
    }
}

// ============================================================
// launch
// ============================================================
extern "C" void kernel_launch(void* const* d_in, const int* in_sizes, int n_in,
                              void* d_out, int out_size)
{
    const float* x      = (const float*)d_in[0];
    const float* ln1_w  = (const float*)d_in[1];
    const float* ln1_b  = (const float*)d_in[2];
    const float* qkv_w  = (const float*)d_in[3];
    const float* qkv_b  = (const float*)d_in[4];
    const float* proj_w = (const float*)d_in[5];
    const float* proj_b = (const float*)d_in[6];
    const float* ln2_w  = (const float*)d_in[7];
    const float* ln2_b  = (const float*)d_in[8];
    const float* fc1_w  = (const float*)d_in[9];
    const float* fc1_b  = (const float*)d_in[10];
    const float* fc2_w  = (const float*)d_in[11];
    const float* fc2_b  = (const float*)d_in[12];
    float* out = (float*)d_out;

    const int M = in_sizes[0] / DIM;   // 8192
    const int B = M / 1024;

    __half *act, *ff, *qkvh, *wq, *wp, *w1, *w2;
    float *x1f;
    cudaGetSymbolAddress((void**)&act,  g_act);
    cudaGetSymbolAddress((void**)&ff,   g_ff);
    cudaGetSymbolAddress((void**)&qkvh, g_qkvh);
    cudaGetSymbolAddress((void**)&x1f,  g_x1);
    cudaGetSymbolAddress((void**)&wq,   g_wq);
    cudaGetSymbolAddress((void**)&wp,   g_wp);
    cudaGetSymbolAddress((void**)&w1,   g_w1);
    cudaGetSymbolAddress((void**)&w2,   g_w2);

    cudaFuncSetAttribute((const void*)flash2,
                         cudaFuncAttributeMaxDynamicSharedMemorySize, FL_SMEM);
    cudaFuncSetAttribute((const void*)hgemm<1>,
                         cudaFuncAttributeMaxDynamicSharedMemorySize, GSM_TOTAL);
    cudaFuncSetAttribute((const void*)hgemm<2>,
                         cudaFuncAttributeMaxDynamicSharedMemorySize, GSM_TOTAL);
    cudaFuncSetAttribute((const void*)hgemm<3>,
                         cudaFuncAttributeMaxDynamicSharedMemorySize, GSM_TOTAL);

    pack_w<<<(3*DIM*DIM + 255)/256, 256>>>(qkv_w,  wq, 3*DIM*DIM);
    pack_w<<<(DIM*DIM   + 255)/256, 256>>>(proj_w, wp, DIM*DIM);
    pack_w<<<(DFF*DIM   + 255)/256, 256>>>(fc1_w,  w1, DFF*DIM);
    pack_w<<<(DIM*DFF   + 255)/256, 256>>>(fc2_w,  w2, DIM*DFF);

    // 1) ln1 -> fp16 act
    ln_pack<<<M, 256>>>(x, ln1_w, ln1_b, act);
    // 2) qkv = act @ Wqkv^T + b  (fp16 out)
    hgemm<3><<<dim3((3*DIM)/128, M/128), 256, GSM_TOTAL>>>(
        act, wq, qkv_b, nullptr, nullptr, qkvh, 3*DIM, DIM);
    // 3) attention (HMMA) -> fp16 act
    flash2<<<dim3(1024/128, B*HEADS), 256, FL_SMEM>>>(qkvh, act);
    // 4) x1 = x + act @ Wproj^T + b
    hgemm<1><<<dim3(DIM/128, M/128), 256, GSM_TOTAL>>>(
        act, wp, proj_b, x, x1f, nullptr, DIM, DIM);
    // 5) ln2 -> fp16 act
    ln_pack<<<M, 256>>>(x1f, ln2_w, ln2_b, act);
    // 6) ff = gelu(act @ Wfc1^T + b)  (fp16 out)
    hgemm<2><<<dim3(DFF/128, M/128), 256, GSM_TOTAL>>>(
        act, w1, fc1_b, nullptr, nullptr, ff, DFF, DIM);
    // 7) out = x1 + ff @ Wfc2^T + b
    hgemm<1><<<dim3(DIM/128, M/128), 256, GSM_TOTAL>>>(
        ff, w2, fc2_b, x1f, out, nullptr, DIM, DFF);
}